// round 12
// baseline (speedup 1.0000x reference)
#include <cuda_runtime.h>
#include <cuda_bf16.h>

#define BATCH 4
#define NP    8192
#define NQ    2048
#define CF    64
#define CT    64
#define KS    32
#define R2    0.04f
#define OUTC  (3 + CF)        // 67 channels in grouped_features

__device__ uint4 g_idx16_v[BATCH * NQ * KS / 8];   // ushort idx, 8 per uint4

// Ball query: whole batch cloud in 96KB dynamic smem (SoA). 1024 threads, one
// query per warp, 64 points/iter, per-warp early exit. Writes ushort idx +
// the 3 centered coord channels.
__global__ __launch_bounds__(1024) void qg_ballquery_kernel(
    const float* __restrict__ coords,
    const float* __restrict__ queries,
    float* __restrict__ out)
{
    extern __shared__ float sxyz[];                  // sx[NP] | sy[NP] | sz[NP]
    float* sx = sxyz;
    __shared__ int slots_s[32][KS];

    int tid  = threadIdx.x;
    int lane = tid & 31;
    int w    = tid >> 5;
    int b    = blockIdx.x >> 6;                      // 64 blocks per batch
    int blk  = blockIdx.x & 63;

    const float* cb = coords + (size_t)b * NP * 3;
    #pragma unroll
    for (int j = 0; j < (NP * 3) / 1024; ++j) {
        int i = tid + j * 1024;
        float v = cb[i];
        int p = i / 3, d = i - 3 * p;
        sxyz[d * NP + p] = v;
    }
    __syncthreads();

    float* sy = sxyz + NP;
    float* sz = sxyz + 2 * NP;
    int* slots = slots_s[w];
    unsigned lt = (1u << lane) - 1u;
    const size_t stride = (size_t)NQ * KS;

    int q = blk * 32 + w;
    int g = b * NQ + q;
    const float* qp = queries + (size_t)g * 3;
    float qx = qp[0], qy = qp[1], qz = qp[2];

    int count = 0;
    for (int base = 0; base < NP; base += 64) {
        int i0 = base + lane, i1 = base + 32 + lane;
        float x0 = sx[i0], y0 = sy[i0], z0 = sz[i0];
        float x1 = sx[i1], y1 = sy[i1], z1 = sz[i1];
        // Match XLA rounding exactly: no FMA contraction.
        float dx0 = __fadd_rn(qx, -x0), dy0 = __fadd_rn(qy, -y0), dz0 = __fadd_rn(qz, -z0);
        float d20 = __fadd_rn(__fadd_rn(__fmul_rn(dx0, dx0), __fmul_rn(dy0, dy0)),
                              __fmul_rn(dz0, dz0));
        float dx1 = __fadd_rn(qx, -x1), dy1 = __fadd_rn(qy, -y1), dz1 = __fadd_rn(qz, -z1);
        float d21 = __fadd_rn(__fadd_rn(__fmul_rn(dx1, dx1), __fmul_rn(dy1, dy1)),
                              __fmul_rn(dz1, dz1));
        bool in0 = d20 < R2;
        bool in1 = d21 < R2;
        unsigned m0 = __ballot_sync(0xffffffffu, in0);
        unsigned m1 = __ballot_sync(0xffffffffu, in1);
        if (in0) {
            int s = count + __popc(m0 & lt);
            if (s < KS) slots[s] = i0;
        }
        int c1 = count + __popc(m0);
        if (in1) {
            int s = c1 + __popc(m1 & lt);
            if (s < KS) slots[s] = i1;
        }
        count = c1 + __popc(m1);
        if (count >= KS) break;
    }
    __syncwarp();

    int cnt   = count < KS ? count : KS;
    int first = (count > 0) ? slots[0] : 0;
    int my    = (lane < cnt) ? slots[lane] : first;
    ((unsigned short*)g_idx16_v)[(size_t)g * KS + lane] = (unsigned short)my;

    size_t ob0 = (size_t)b * OUTC * stride + (size_t)q * KS + lane;
    out[ob0]              = sx[my] - qx;
    out[ob0 + stride]     = sy[my] - qy;
    out[ob0 + 2 * stride] = sz[my] - qz;
}

// Gather: block per (batch, channel QUAD, query-chunk) = 4*32*4 = 512 blocks.
// Four channel rows interleaved as float4 in 128KB smem (one LDS.128 -> 4 ch).
// idx as ushort: one uint4 load = 8 indices. Prefetch next group.
__global__ __launch_bounds__(512) void qg_gather_kernel(
    const float* __restrict__ feats,
    const float* __restrict__ temb,
    float* __restrict__ out)
{
    extern __shared__ float4 rows4[];    // [NP] (128KB)

    int tid   = threadIdx.x;
    int bc    = blockIdx.x;              // 0..511
    int chunk = bc & 3;
    int quad  = (bc >> 2) & 31;
    int b     = bc >> 7;
    int cc    = quad * 4;                // 0..124
    int which = cc >> 6;
    int ch    = cc & 63;

    const float* s0 = (which ? temb : feats) + ((size_t)b * 64 + ch) * NP;
    // Fill: lane-contiguous STS.128 (conflict-free), coalesced scalar LDG.
    for (int p = tid; p < NP; p += 512)
        rows4[p] = make_float4(s0[p], s0[NP + p], s0[2 * NP + p], s0[3 * NP + p]);
    __syncthreads();

    const size_t stride = (size_t)NQ * KS;
    size_t ob0;
    if (which == 0)
        ob0 = (size_t)b * OUTC * stride + (size_t)(3 + ch) * stride;
    else
        ob0 = (size_t)BATCH * OUTC * stride + (size_t)b * CT * stride + (size_t)ch * stride;

    const uint4* idxp = g_idx16_v + (size_t)b * (NQ * KS / 8);
    // 8192 groups-of-8 per batch; 2048 per chunk; 512 threads -> 4 iterations.
    int e = chunk * 2048 + tid;
    uint4 raw = idxp[e];

    #pragma unroll
    for (int it = 0; it < 4; ++it) {
        uint4 nxt;
        if (it < 3) nxt = idxp[e + (it + 1) * 512];
        int u0 = raw.x & 0xffff, u1 = raw.x >> 16;
        int u2 = raw.y & 0xffff, u3 = raw.y >> 16;
        int u4 = raw.z & 0xffff, u5 = raw.z >> 16;
        int u6 = raw.w & 0xffff, u7 = raw.w >> 16;
        float4 f0 = rows4[u0], f1 = rows4[u1], f2 = rows4[u2], f3 = rows4[u3];
        float4 f4 = rows4[u4], f5 = rows4[u5], f6 = rows4[u6], f7 = rows4[u7];
        size_t pe = (size_t)(e + it * 512) * 8;
        float* o0 = out + ob0 + pe;
        *(float4*)(o0)                  = make_float4(f0.x, f1.x, f2.x, f3.x);
        *(float4*)(o0 + 4)              = make_float4(f4.x, f5.x, f6.x, f7.x);
        *(float4*)(o0 + stride)         = make_float4(f0.y, f1.y, f2.y, f3.y);
        *(float4*)(o0 + stride + 4)     = make_float4(f4.y, f5.y, f6.y, f7.y);
        *(float4*)(o0 + 2 * stride)     = make_float4(f0.z, f1.z, f2.z, f3.z);
        *(float4*)(o0 + 2 * stride + 4) = make_float4(f4.z, f5.z, f6.z, f7.z);
        *(float4*)(o0 + 3 * stride)     = make_float4(f0.w, f1.w, f2.w, f3.w);
        *(float4*)(o0 + 3 * stride + 4) = make_float4(f4.w, f5.w, f6.w, f7.w);
        raw = nxt;
    }
}

extern "C" void kernel_launch(void* const* d_in, const int* in_sizes, int n_in,
                              void* d_out, int out_size) {
    const float* coords  = (const float*)d_in[0];  // [B,Np,3]
    const float* feats   = (const float*)d_in[1];  // [B,C,Np]
    const float* temb    = (const float*)d_in[2];  // [B,Ct,Np]
    const float* queries = (const float*)d_in[3];  // [B,Nq,3]
    float* out = (float*)d_out;

    const int bq_smem = 3 * NP * (int)sizeof(float);    // 96KB
    const int gt_smem = NP * (int)sizeof(float4);       // 128KB
    cudaFuncSetAttribute(qg_ballquery_kernel,
                         cudaFuncAttributeMaxDynamicSharedMemorySize, bq_smem);
    cudaFuncSetAttribute(qg_gather_kernel,
                         cudaFuncAttributeMaxDynamicSharedMemorySize, gt_smem);

    qg_ballquery_kernel<<<BATCH * 64, 1024, bq_smem>>>(coords, queries, out);
    qg_gather_kernel<<<512, 512, gt_smem>>>(feats, temb, out);
}

// round 13
// speedup vs baseline: 1.7144x; 1.7144x over previous
#include <cuda_runtime.h>
#include <cuda_bf16.h>

#define BATCH 4
#define NP    8192
#define NQ    2048
#define CF    64
#define CT    64
#define KS    32
#define R2    0.04f
#define OUTC  (3 + CF)        // 67 channels in grouped_features
#define QPB   64              // queries per ball-query block

__device__ uint2 g_idx16_v[BATCH * NQ * KS / 4];   // ushort idx, 4 per uint2

// Ball query: whole batch cloud in 96KB dynamic smem (SoA). 128 blocks (single
// wave even at 1 block/SM), 1024 threads, 2 queries per warp, 64 pts/iter.
__global__ __launch_bounds__(1024) void qg_ballquery_kernel(
    const float* __restrict__ coords,
    const float* __restrict__ queries,
    float* __restrict__ out)
{
    extern __shared__ float sxyz[];                  // sx[NP] | sy[NP] | sz[NP]
    float* sx = sxyz;
    __shared__ int slots_s[32][KS];

    int tid  = threadIdx.x;
    int lane = tid & 31;
    int w    = tid >> 5;
    int b    = blockIdx.x >> 5;                      // 32 blocks per batch
    int blk  = blockIdx.x & 31;

    const float* cb = coords + (size_t)b * NP * 3;
    #pragma unroll
    for (int j = 0; j < (NP * 3) / 1024; ++j) {
        int i = tid + j * 1024;
        float v = cb[i];
        int p = i / 3, d = i - 3 * p;
        sxyz[d * NP + p] = v;
    }
    __syncthreads();

    float* sy = sxyz + NP;
    float* sz = sxyz + 2 * NP;
    int* slots = slots_s[w];
    unsigned lt = (1u << lane) - 1u;
    const size_t stride = (size_t)NQ * KS;

    #pragma unroll
    for (int j = 0; j < 2; ++j) {
        int q = blk * QPB + w + 32 * j;
        int g = b * NQ + q;
        const float* qp = queries + (size_t)g * 3;
        float qx = qp[0], qy = qp[1], qz = qp[2];

        int count = 0;
        for (int base = 0; base < NP; base += 64) {
            int i0 = base + lane, i1 = base + 32 + lane;
            float x0 = sx[i0], y0 = sy[i0], z0 = sz[i0];
            float x1 = sx[i1], y1 = sy[i1], z1 = sz[i1];
            // Match XLA rounding exactly: no FMA contraction.
            float dx0 = __fadd_rn(qx, -x0), dy0 = __fadd_rn(qy, -y0), dz0 = __fadd_rn(qz, -z0);
            float d20 = __fadd_rn(__fadd_rn(__fmul_rn(dx0, dx0), __fmul_rn(dy0, dy0)),
                                  __fmul_rn(dz0, dz0));
            float dx1 = __fadd_rn(qx, -x1), dy1 = __fadd_rn(qy, -y1), dz1 = __fadd_rn(qz, -z1);
            float d21 = __fadd_rn(__fadd_rn(__fmul_rn(dx1, dx1), __fmul_rn(dy1, dy1)),
                                  __fmul_rn(dz1, dz1));
            bool in0 = d20 < R2;
            bool in1 = d21 < R2;
            unsigned m0 = __ballot_sync(0xffffffffu, in0);
            unsigned m1 = __ballot_sync(0xffffffffu, in1);
            if (in0) {
                int s = count + __popc(m0 & lt);
                if (s < KS) slots[s] = i0;
            }
            int c1 = count + __popc(m0);
            if (in1) {
                int s = c1 + __popc(m1 & lt);
                if (s < KS) slots[s] = i1;
            }
            count = c1 + __popc(m1);
            if (count >= KS) break;
        }
        __syncwarp();

        int cnt   = count < KS ? count : KS;
        int first = (count > 0) ? slots[0] : 0;
        int my    = (lane < cnt) ? slots[lane] : first;
        ((unsigned short*)g_idx16_v)[(size_t)g * KS + lane] = (unsigned short)my;

        size_t ob0 = (size_t)b * OUTC * stride + (size_t)q * KS + lane;
        out[ob0]              = sx[my] - qx;
        out[ob0 + stride]     = sy[my] - qy;
        out[ob0 + 2 * stride] = sz[my] - qz;
        __syncwarp();
    }
}

// Gather: block per (batch, channel-pair, query-chunk) = 512 blocks, 64KB smem.
// ushort idx: uint2 load = 4 indices. FOUR independent prefetched streams.
__global__ __launch_bounds__(256) void qg_gather_kernel(
    const float* __restrict__ feats,
    const float* __restrict__ temb,
    float* __restrict__ out)
{
    extern __shared__ float2 rows[];    // [NP] interleaved channel pair (64KB)

    int tid   = threadIdx.x;
    int bc    = blockIdx.x;             // 0..511
    int chunk = bc & 1;
    int pair  = (bc >> 1) & 63;
    int b     = bc >> 7;
    int cc    = pair * 2;               // 0..126
    int which = cc >> 6;
    int ch    = cc & 63;

    const float* s0 = (which ? temb : feats) + ((size_t)b * 64 + ch) * NP;
    for (int p = tid; p < NP; p += 256)
        rows[p] = make_float2(s0[p], s0[NP + p]);
    __syncthreads();

    const size_t stride = (size_t)NQ * KS;
    size_t ob0;
    if (which == 0)
        ob0 = (size_t)b * OUTC * stride + (size_t)(3 + ch) * stride;
    else
        ob0 = (size_t)BATCH * OUTC * stride + (size_t)b * CT * stride + (size_t)ch * stride;
    size_t ob1 = ob0 + stride;

    // Per batch: 16384 uint2 groups (4 elems each); this chunk: 8192 groups.
    const uint2* idxp = g_idx16_v + (size_t)b * (NQ * KS / 4) + chunk * 8192;

    // 4 streams of 2048 groups; 8 iterations; prefetch next iteration's loads.
    uint2 cur0 = idxp[0 * 2048 + tid];
    uint2 cur1 = idxp[1 * 2048 + tid];
    uint2 cur2 = idxp[2 * 2048 + tid];
    uint2 cur3 = idxp[3 * 2048 + tid];

    #pragma unroll
    for (int it = 0; it < 8; ++it) {
        uint2 n0, n1, n2, n3;
        if (it < 7) {
            int o = (it + 1) * 256 + tid;
            n0 = idxp[0 * 2048 + o];
            n1 = idxp[1 * 2048 + o];
            n2 = idxp[2 * 2048 + o];
            n3 = idxp[3 * 2048 + o];
        }
        #pragma unroll
        for (int s = 0; s < 4; ++s) {
            uint2 u = (s == 0) ? cur0 : (s == 1) ? cur1 : (s == 2) ? cur2 : cur3;
            int ge = s * 2048 + it * 256 + tid + chunk * 8192;   // group id in batch
            float2 f0 = rows[u.x & 0xffff];
            float2 f1 = rows[u.x >> 16];
            float2 f2 = rows[u.y & 0xffff];
            float2 f3 = rows[u.y >> 16];
            size_t pe = (size_t)ge * 4;
            *(float4*)(out + ob0 + pe) = make_float4(f0.x, f1.x, f2.x, f3.x);
            *(float4*)(out + ob1 + pe) = make_float4(f0.y, f1.y, f2.y, f3.y);
        }
        cur0 = n0; cur1 = n1; cur2 = n2; cur3 = n3;
    }
}

extern "C" void kernel_launch(void* const* d_in, const int* in_sizes, int n_in,
                              void* d_out, int out_size) {
    const float* coords  = (const float*)d_in[0];  // [B,Np,3]
    const float* feats   = (const float*)d_in[1];  // [B,C,Np]
    const float* temb    = (const float*)d_in[2];  // [B,Ct,Np]
    const float* queries = (const float*)d_in[3];  // [B,Nq,3]
    float* out = (float*)d_out;

    const int bq_smem = 3 * NP * (int)sizeof(float);    // 96KB
    const int gt_smem = NP * (int)sizeof(float2);       // 64KB
    cudaFuncSetAttribute(qg_ballquery_kernel,
                         cudaFuncAttributeMaxDynamicSharedMemorySize, bq_smem);
    cudaFuncSetAttribute(qg_gather_kernel,
                         cudaFuncAttributeMaxDynamicSharedMemorySize, gt_smem);

    qg_ballquery_kernel<<<BATCH * 32, 1024, bq_smem>>>(coords, queries, out);
    qg_gather_kernel<<<512, 256, gt_smem>>>(feats, temb, out);
}